// round 9
// baseline (speedup 1.0000x reference)
#include <cuda_runtime.h>
#include <math.h>
#include <stdint.h>

#define NLEVELS   16
#define NENTRIES  524309u

struct Meta {
    float rinv[NLEVELS]; // RN_f32(1/es) — XLA constant-folded reciprocal
    int   en[NLEVELS];
    int   start_hash;
};

__device__ __forceinline__ float2 ldg_cg_f2(const float2* p) {
    float2 r;
    asm("ld.global.cg.v2.f32 {%0,%1}, [%2];" : "=f"(r.x), "=f"(r.y) : "l"(p));
    return r;
}

// R7 structure (1 point per warp, 2 lanes per (point,level), 32 regs, occ ~87%)
// + ONE change: hashed-level gathers use .cg (L2-only) so the 42MB of random
// hashed traffic stops evicting the 6.6MB of dense tables from L1.
__global__ __launch_bounds__(256)
void hashgrid_fwd_kernel(const float* __restrict__ xyz,
                         const float2* __restrict__ data,
                         float2* __restrict__ out,
                         Meta meta, int total)
{
    int t = blockIdx.x * blockDim.x + threadIdx.x;
    if (t >= total) return;
    int n  = t >> 5;          // point index
    int ll = t & 31;
    int l  = ll >> 1;         // level
    int h  = ll & 1;          // z-half

    float px = __fadd_rn(__ldg(xyz + 3 * n + 0), 1.0f);
    float py = __fadd_rn(__ldg(xyz + 3 * n + 1), 1.0f);
    float pz = __fadd_rn(__ldg(xyz + 3 * n + 2), 1.0f);

    float rinv = meta.rinv[l];
    int   en   = meta.en[l];

    // XLA divide-by-constant: f = RN(p * RN(1/es))
    float fx = __fmul_rn(px, rinv);
    float fy = __fmul_rn(py, rinv);
    float fz = __fmul_rn(pz, rinv);

    // quirk-faithful corners: int32(f + off), fp32 add per corner
    int x0 = (int)fx;  int x1 = (int)__fadd_rn(fx, 1.0f);
    int y0 = (int)fy;  int y1 = (int)__fadd_rn(fy, 1.0f);
    int z0 = (int)fz;  int z1 = (int)__fadd_rn(fz, 1.0f);

    float ox = __fadd_rn(fx, -(float)x0);
    float oy = __fadd_rn(fy, -(float)y0);
    float oz = __fadd_rn(fz, -(float)z0);

    int em = en - 1;
    x0 = min(max(x0, 0), em);   x1 = min(max(x1, 0), em);
    y0 = min(max(y0, 0), em);   y1 = min(max(y1, 0), em);
    int zc = h ? z1 : z0;
    zc = min(max(zc, 0), em);

    bool hashed = (l >= meta.start_hash);

    uint64_t hxa[2] = { (uint64_t)(uint32_t)x0, (uint64_t)(uint32_t)x1 };
    uint64_t hya[2] = { (uint64_t)(uint32_t)y0 * 19349663ull,
                        (uint64_t)(uint32_t)y1 * 19349663ull };
    uint64_t hz     = (uint64_t)(uint32_t)zc * 83492791ull;

    unsigned ue  = (unsigned)en;
    unsigned dxa[2] = { (unsigned)x0 * ue * ue, (unsigned)x1 * ue * ue };
    unsigned dya[2] = { (unsigned)y0 * ue,      (unsigned)y1 * ue };
    unsigned dz     = (unsigned)zc;

    const float2* __restrict__ tbl = data + (size_t)l * NENTRIES;

    float wxa[2] = { __saturatef(__fadd_rn(1.0f, -ox)), __saturatef(ox) };
    float wya[2] = { __saturatef(__fadd_rn(1.0f, -oy)), __saturatef(oy) };
    float wz     = h ? __saturatef(oz) : __saturatef(__fadd_rn(1.0f, -oz));

    unsigned idx[4];
#pragma unroll
    for (int c = 0; c < 4; c++) {
        int bx = (c >> 1) & 1, by = c & 1;
        unsigned hidx = (unsigned)((hxa[bx] ^ hya[by] ^ hz) % (uint64_t)NENTRIES);
        unsigned didx = dxa[bx] + dya[by] + dz;
        idx[c] = hashed ? hidx : didx;
    }

    // issue all 4 gathers first (MLP=4); lane pairs coalesce on dense levels
    float2 v[4];
    if (hashed) {
#pragma unroll
        for (int c = 0; c < 4; c++) v[c] = ldg_cg_f2(&tbl[idx[c]]);
    } else {
#pragma unroll
        for (int c = 0; c < 4; c++) v[c] = __ldg(&tbl[idx[c]]);
    }

    float accx = 0.0f, accy = 0.0f;
#pragma unroll
    for (int c = 0; c < 4; c++) {
        int bx = (c >> 1) & 1, by = c & 1;
        float w = __fmul_rn(__fmul_rn(wxa[bx], wya[by]), wz);
        accx = __fadd_rn(accx, __fmul_rn(w, v[c].x));
        accy = __fadd_rn(accy, __fmul_rn(w, v[c].y));
    }

    // combine z-halves within the lane pair; even lane stores coalesced
    accx = __fadd_rn(accx, __shfl_xor_sync(0xFFFFFFFFu, accx, 1));
    accy = __fadd_rn(accy, __shfl_xor_sync(0xFFFFFFFFu, accy, 1));
    if (h == 0)
        out[(size_t)n * NLEVELS + l] = make_float2(accx, accy);
}

extern "C" void kernel_launch(void* const* d_in, const int* in_sizes, int n_in,
                              void* d_out, int out_size)
{
    const float* xyz  = (const float*)d_in[0];
    const float* data = (const float*)d_in[1];
    int sx = in_sizes[0], sd = in_sizes[1];
    if (sx > sd) {
        const float* tmp = xyz; xyz = data; data = tmp;
        int ts = sx; sx = sd; sd = ts;
    }
    int npoints = sx / 3;

    // numpy _grid_meta() bit-exact via runtime libm pow (volatile blocks folding)
    static volatile double V_B = 1.38;
    static volatile double V_BASE = 16.0;
    static volatile double V_THIRD_NUM = 1.0;
    Meta m;
    m.start_hash = NLEVELS;
    double third = V_THIRD_NUM / 3.0;
    for (int i = 0; i < NLEVELS; i++) {
        double b   = V_B;
        double res = V_BASE * pow(b, (double)i);
        double vnd = pow(res, 3.0);
        long long vn = (long long)vnd;
        double vs  = pow(8.0 / (double)vn, third);
        long long en = (long long)(2.0 / vs);
        double esd = 2.0 / ((double)en - 1.0);
        float  esf = (float)esd;
        m.en[i]   = (int)en;
        m.rinv[i] = 1.0f / esf;
        if (m.start_hash == NLEVELS && vn > (long long)NENTRIES)
            m.start_hash = i;
    }

    int total = npoints * 32;   // 2 threads per (point, level)
    int threads = 256;
    int blocks = (total + threads - 1) / threads;
    hashgrid_fwd_kernel<<<blocks, threads>>>(
        xyz, (const float2*)data, (float2*)d_out, m, total);
}

// round 10
// speedup vs baseline: 1.2708x; 1.2708x over previous
#include <cuda_runtime.h>
#include <math.h>
#include <stdint.h>

#define NLEVELS   16
#define NENTRIES  524309u

struct Meta {
    float rinv[NLEVELS]; // RN_f32(1/es) — XLA constant-folded reciprocal
    int   en[NLEVELS];
    int   start_hash;
};

// R7 layout: warp = 1 point; lane = (level, z-half). Lane pair (2k,2k+1)
// shares (point, level) and differs only in the z corner, so dense-level
// gathers coalesce pairwise into one 128B line (one L1 wavefront).
// xyz is fetched by ONE LDG on 3 lanes + SHFL broadcast (saves ~2 wf/point
// vs three all-lane broadcast loads).
__global__ __launch_bounds__(256)
void hashgrid_fwd_kernel(const float* __restrict__ xyz,
                         const float2* __restrict__ data,
                         float2* __restrict__ out,
                         Meta meta, int total)
{
    int t = blockIdx.x * blockDim.x + threadIdx.x;
    if (t >= total) return;
    int n  = t >> 5;          // point index (warp-uniform)
    int ll = t & 31;
    int l  = ll >> 1;         // level
    int h  = ll & 1;          // z-half

    // one gather instruction, 3 active lanes, then broadcast via shuffle
    float c = 0.0f;
    if (ll < 3) c = __ldg(xyz + 3 * n + ll);
    float px = __fadd_rn(__shfl_sync(0xFFFFFFFFu, c, 0), 1.0f);
    float py = __fadd_rn(__shfl_sync(0xFFFFFFFFu, c, 1), 1.0f);
    float pz = __fadd_rn(__shfl_sync(0xFFFFFFFFu, c, 2), 1.0f);

    float rinv = meta.rinv[l];
    int   en   = meta.en[l];

    // XLA divide-by-constant: f = RN(p * RN(1/es))
    float fx = __fmul_rn(px, rinv);
    float fy = __fmul_rn(py, rinv);
    float fz = __fmul_rn(pz, rinv);

    // quirk-faithful corners: int32(f + off), fp32 add per corner
    int x0 = (int)fx;  int x1 = (int)__fadd_rn(fx, 1.0f);
    int y0 = (int)fy;  int y1 = (int)__fadd_rn(fy, 1.0f);
    int z0 = (int)fz;  int z1 = (int)__fadd_rn(fz, 1.0f);

    // offsets from UNclipped corner 0 (exact)
    float ox = __fadd_rn(fx, -(float)x0);
    float oy = __fadd_rn(fy, -(float)y0);
    float oz = __fadd_rn(fz, -(float)z0);

    int em = en - 1;
    x0 = min(max(x0, 0), em);   x1 = min(max(x1, 0), em);
    y0 = min(max(y0, 0), em);   y1 = min(max(y1, 0), em);
    int zc = h ? z1 : z0;
    zc = min(max(zc, 0), em);

    bool hashed = (l >= meta.start_hash);

    // int64-semantics hash terms (PS = {1, 19349663, 83492791})
    uint64_t hxa[2] = { (uint64_t)(uint32_t)x0, (uint64_t)(uint32_t)x1 };
    uint64_t hya[2] = { (uint64_t)(uint32_t)y0 * 19349663ull,
                        (uint64_t)(uint32_t)y1 * 19349663ull };
    uint64_t hz     = (uint64_t)(uint32_t)zc * 83492791ull;

    unsigned ue  = (unsigned)en;
    unsigned dxa[2] = { (unsigned)x0 * ue * ue, (unsigned)x1 * ue * ue };
    unsigned dya[2] = { (unsigned)y0 * ue,      (unsigned)y1 * ue };
    unsigned dz     = (unsigned)zc;

    const float2* __restrict__ tbl = data + (size_t)l * NENTRIES;

    float wxa[2] = { __saturatef(__fadd_rn(1.0f, -ox)), __saturatef(ox) };
    float wya[2] = { __saturatef(__fadd_rn(1.0f, -oy)), __saturatef(oy) };
    float wz     = h ? __saturatef(oz) : __saturatef(__fadd_rn(1.0f, -oz));

    unsigned idx[4];
#pragma unroll
    for (int cc = 0; cc < 4; cc++) {
        int bx = (cc >> 1) & 1, by = cc & 1;
        unsigned hidx = (unsigned)((hxa[bx] ^ hya[by] ^ hz) % (uint64_t)NENTRIES);
        unsigned didx = dxa[bx] + dya[by] + dz;
        idx[cc] = hashed ? hidx : didx;
    }

    // issue all 4 gathers first (MLP=4); default .ca caching (R9 proved .cg -27%)
    float2 v[4];
#pragma unroll
    for (int cc = 0; cc < 4; cc++) v[cc] = __ldg(&tbl[idx[cc]]);

    float accx = 0.0f, accy = 0.0f;
#pragma unroll
    for (int cc = 0; cc < 4; cc++) {
        int bx = (cc >> 1) & 1, by = cc & 1;
        float w = __fmul_rn(__fmul_rn(wxa[bx], wya[by]), wz);
        accx = __fadd_rn(accx, __fmul_rn(w, v[cc].x));
        accy = __fadd_rn(accy, __fmul_rn(w, v[cc].y));
    }

    // combine z-halves within the lane pair; even lanes store 128B coalesced
    accx = __fadd_rn(accx, __shfl_xor_sync(0xFFFFFFFFu, accx, 1));
    accy = __fadd_rn(accy, __shfl_xor_sync(0xFFFFFFFFu, accy, 1));
    if (h == 0)
        out[(size_t)n * NLEVELS + l] = make_float2(accx, accy);
}

extern "C" void kernel_launch(void* const* d_in, const int* in_sizes, int n_in,
                              void* d_out, int out_size)
{
    const float* xyz  = (const float*)d_in[0];
    const float* data = (const float*)d_in[1];
    int sx = in_sizes[0], sd = in_sizes[1];
    if (sx > sd) {
        const float* tmp = xyz; xyz = data; data = tmp;
        int ts = sx; sx = sd; sd = ts;
    }
    int npoints = sx / 3;

    // numpy _grid_meta() bit-exact via runtime libm pow (volatile blocks folding)
    static volatile double V_B = 1.38;
    static volatile double V_BASE = 16.0;
    static volatile double V_THIRD_NUM = 1.0;
    Meta m;
    m.start_hash = NLEVELS;
    double third = V_THIRD_NUM / 3.0;
    for (int i = 0; i < NLEVELS; i++) {
        double b   = V_B;
        double res = V_BASE * pow(b, (double)i);    // BASE_RES * B**i
        double vnd = pow(res, 3.0);                 // (...)**3
        long long vn = (long long)vnd;              // int() truncation
        double vs  = pow(8.0 / (double)vn, third);  // (prod/vn)**(1/3)
        long long en = (long long)(2.0 / vs);       // astype(int64) truncation
        double esd = 2.0 / ((double)en - 1.0);
        float  esf = (float)esd;                    // f32 es (jnp.asarray cast)
        m.en[i]   = (int)en;
        m.rinv[i] = 1.0f / esf;                     // IEEE f32 reciprocal (XLA fold)
        if (m.start_hash == NLEVELS && vn > (long long)NENTRIES)
            m.start_hash = i;
    }

    int total = npoints * 32;   // 2 threads per (point, level)
    int threads = 256;
    int blocks = (total + threads - 1) / threads;
    hashgrid_fwd_kernel<<<blocks, threads>>>(
        xyz, (const float2*)data, (float2*)d_out, m, total);
}

// round 11
// speedup vs baseline: 1.3102x; 1.0310x over previous
#include <cuda_runtime.h>
#include <math.h>
#include <stdint.h>

#define NLEVELS   16
#define NENTRIES  524309u

struct Meta {
    float rinv[NLEVELS]; // RN_f32(1/es) — XLA constant-folded reciprocal
    int   en[NLEVELS];
    int   start_hash;
};

// Converged layout (R7): warp = 1 point; lane = (level, z-half).
// Lane pair (2k,2k+1) shares (point,level), differs in z corner -> dense-level
// gathers coalesce pairwise into one 128B line. All 4 gathers issue before any
// weight math (loads fill the latency shadow). 128-thread blocks for finer
// per-SM scheduling granularity at identical occupancy (32 regs).
__global__ __launch_bounds__(128)
void hashgrid_fwd_kernel(const float* __restrict__ xyz,
                         const float2* __restrict__ data,
                         float2* __restrict__ out,
                         Meta meta, int total)
{
    int t = blockIdx.x * blockDim.x + threadIdx.x;
    if (t >= total) return;
    int n  = t >> 5;          // point index (warp-uniform)
    int ll = t & 31;
    int l  = ll >> 1;         // level
    int h  = ll & 1;          // z-half

    // broadcast loads (1 wf each, L1-hot; measured cheaper than ldg+3xSHFL)
    float px = __fadd_rn(__ldg(xyz + 3 * n + 0), 1.0f);
    float py = __fadd_rn(__ldg(xyz + 3 * n + 1), 1.0f);
    float pz = __fadd_rn(__ldg(xyz + 3 * n + 2), 1.0f);

    float rinv = meta.rinv[l];
    int   en   = meta.en[l];

    // XLA divide-by-constant: f = RN(p * RN(1/es))
    float fx = __fmul_rn(px, rinv);
    float fy = __fmul_rn(py, rinv);
    float fz = __fmul_rn(pz, rinv);

    // quirk-faithful corners: int32(f + off), fp32 add per corner
    int x0 = (int)fx;  int x1 = (int)__fadd_rn(fx, 1.0f);
    int y0 = (int)fy;  int y1 = (int)__fadd_rn(fy, 1.0f);
    int z0 = (int)fz;  int z1 = (int)__fadd_rn(fz, 1.0f);

    // offsets from UNclipped corner 0 (exact)
    float ox = __fadd_rn(fx, -(float)x0);
    float oy = __fadd_rn(fy, -(float)y0);
    float oz = __fadd_rn(fz, -(float)z0);

    int em = en - 1;
    x0 = min(max(x0, 0), em);   x1 = min(max(x1, 0), em);
    y0 = min(max(y0, 0), em);   y1 = min(max(y1, 0), em);
    int zc = h ? z1 : z0;
    zc = min(max(zc, 0), em);

    bool hashed = (l >= meta.start_hash);

    // int64-semantics hash terms (PS = {1, 19349663, 83492791})
    uint64_t hxa[2] = { (uint64_t)(uint32_t)x0, (uint64_t)(uint32_t)x1 };
    uint64_t hya[2] = { (uint64_t)(uint32_t)y0 * 19349663ull,
                        (uint64_t)(uint32_t)y1 * 19349663ull };
    uint64_t hz     = (uint64_t)(uint32_t)zc * 83492791ull;

    unsigned ue  = (unsigned)en;
    unsigned dxa[2] = { (unsigned)x0 * ue * ue, (unsigned)x1 * ue * ue };
    unsigned dya[2] = { (unsigned)y0 * ue,      (unsigned)y1 * ue };
    unsigned dz     = (unsigned)zc;

    const float2* __restrict__ tbl = data + (size_t)l * NENTRIES;

    // indices first...
    unsigned idx[4];
#pragma unroll
    for (int c = 0; c < 4; c++) {
        int bx = (c >> 1) & 1, by = c & 1;
        unsigned hidx = (unsigned)((hxa[bx] ^ hya[by] ^ hz) % (uint64_t)NENTRIES);
        unsigned didx = dxa[bx] + dya[by] + dz;
        idx[c] = hashed ? hidx : didx;
    }

    // ...then ALL gathers (MLP=4, default .ca — R9 proved .cg -27%)...
    float2 v[4];
#pragma unroll
    for (int c = 0; c < 4; c++) v[c] = __ldg(&tbl[idx[c]]);

    // ...weight math lives in the load shadow
    float wxa[2] = { __saturatef(__fadd_rn(1.0f, -ox)), __saturatef(ox) };
    float wya[2] = { __saturatef(__fadd_rn(1.0f, -oy)), __saturatef(oy) };
    float wz     = h ? __saturatef(oz) : __saturatef(__fadd_rn(1.0f, -oz));

    float accx = 0.0f, accy = 0.0f;
#pragma unroll
    for (int c = 0; c < 4; c++) {
        int bx = (c >> 1) & 1, by = c & 1;
        float w = __fmul_rn(__fmul_rn(wxa[bx], wya[by]), wz);
        accx = __fadd_rn(accx, __fmul_rn(w, v[c].x));
        accy = __fadd_rn(accy, __fmul_rn(w, v[c].y));
    }

    // combine z-halves within the lane pair; even lanes store 128B coalesced
    accx = __fadd_rn(accx, __shfl_xor_sync(0xFFFFFFFFu, accx, 1));
    accy = __fadd_rn(accy, __shfl_xor_sync(0xFFFFFFFFu, accy, 1));
    if (h == 0)
        out[(size_t)n * NLEVELS + l] = make_float2(accx, accy);
}

extern "C" void kernel_launch(void* const* d_in, const int* in_sizes, int n_in,
                              void* d_out, int out_size)
{
    const float* xyz  = (const float*)d_in[0];
    const float* data = (const float*)d_in[1];
    int sx = in_sizes[0], sd = in_sizes[1];
    if (sx > sd) {
        const float* tmp = xyz; xyz = data; data = tmp;
        int ts = sx; sx = sd; sd = ts;
    }
    int npoints = sx / 3;

    // numpy _grid_meta() bit-exact via runtime libm pow (volatile blocks folding)
    static volatile double V_B = 1.38;
    static volatile double V_BASE = 16.0;
    static volatile double V_THIRD_NUM = 1.0;
    Meta m;
    m.start_hash = NLEVELS;
    double third = V_THIRD_NUM / 3.0;
    for (int i = 0; i < NLEVELS; i++) {
        double b   = V_B;
        double res = V_BASE * pow(b, (double)i);    // BASE_RES * B**i
        double vnd = pow(res, 3.0);                 // (...)**3
        long long vn = (long long)vnd;              // int() truncation
        double vs  = pow(8.0 / (double)vn, third);  // (prod/vn)**(1/3)
        long long en = (long long)(2.0 / vs);       // astype(int64) truncation
        double esd = 2.0 / ((double)en - 1.0);
        float  esf = (float)esd;                    // f32 es (jnp.asarray cast)
        m.en[i]   = (int)en;
        m.rinv[i] = 1.0f / esf;                     // IEEE f32 reciprocal (XLA fold)
        if (m.start_hash == NLEVELS && vn > (long long)NENTRIES)
            m.start_hash = i;
    }

    int total = npoints * 32;   // 2 threads per (point, level)
    int threads = 128;          // 16 blocks/SM at 32 regs — finer scheduling
    int blocks = (total + threads - 1) / threads;
    hashgrid_fwd_kernel<<<blocks, threads>>>(
        xyz, (const float2*)data, (float2*)d_out, m, total);
}